// round 11
// baseline (speedup 1.0000x reference)
#include <cuda_runtime.h>
#include <cuda_bf16.h>

// DETR post-processor, SINGLE kernel with role-split grid (expected shape):
//   bid <  256 : SORTER CTA for batch bid. Thread0 spin-waits (volatile +
//                nanosleep) on g_done[batch]==8, acquire-fences, then the CTA
//                bitonic-sorts the <=1024 candidates (512 thr x 2: shfl j<=16,
//                local j=32, smem j>=64) and decodes the top-300 straight from
//                registers. Sorts overlap streaming; only the last wave's
//                batches are exposed (~6us). Counters self-reset.
//   bid >= 256 : STREAMER CTA (batch (bid-256)/8, segment (bid-256)%8).
//                R7's proven scan body: FMNMX screen at t=2.4 -> smem buffer,
//                one global atomic reserves a g_cand block, coalesced flush,
//                threadfence + done-increment. Streaming measured at the LTS
//                ceiling (~6.3 TB/s); 188+ concurrent streamers keep it there.
//   No deadlock: 256 sorters < 444 guaranteed-resident CTAs; every streamer
//   increments done (incl. overflow-poison path). Exact histogram fallback in
//   the sorter if count outside [300,1024] (lambda=656, sigma=26 -> never).
//   Generic shape -> separate scan_generic + rank_kernel pipeline.

#define NCLS    80
#define NQ      1000
#define NPB     80000
#define NF4B    20000          // float4 per batch
#define NB      256
#define TOPK    300
#define CAP     1024
#define THR     2.4f
#define SEGS    8              // streamer CTAs per batch
#define SEGF4   2500           // float4 per streamer CTA
#define SCTA    512
#define BUFCAP  384            // smem candidate buffer (expect 82, sigma 9)
#define GPAD    32             // counter stride (128B) -> spread LTS slices
#define NHIST   4096

__device__ unsigned long long g_cand[NB][CAP];
__device__ int g_cnt[NB * GPAD];
__device__ int g_done[NB * GPAD];

__device__ __forceinline__ unsigned fkey(float f) {
    unsigned u = __float_as_uint(f);
    return (u & 0x80000000u) ? ~u : (u | 0x80000000u);  // monotonic float->uint
}
__device__ __forceinline__ float key2f(unsigned k) {
    return (k & 0x80000000u) ? __uint_as_float(k & 0x7fffffffu)
                             : __uint_as_float(~k);
}
__device__ __forceinline__ unsigned long long pack(float val, unsigned loc) {
    return ((unsigned long long)fkey(val) << 32) | (unsigned)(0xFFFFFFFFu - loc);
}

// ---- bitonic helpers (element index i, phase j, block k) ----
__device__ __forceinline__ unsigned long long upick(
    unsigned long long v, unsigned long long o, int i, int j, int k)
{
    const bool keep_max = (((i & j) == 0) == ((i & k) == 0));
    const unsigned long long mx = v > o ? v : o;
    const unsigned long long mn = v > o ? o : v;
    return keep_max ? mx : mn;
}
__device__ __forceinline__ unsigned long long ushfl(
    unsigned long long v, int i, int j, int k)
{
    const unsigned long long o = __shfl_xor_sync(0xFFFFFFFFu, v, j);
    return upick(v, o, i, j, k);
}
__device__ __forceinline__ void ulocal32(
    unsigned long long& r0, unsigned long long& r1, int i0, int k)
{
    const bool desc = ((i0 & k) == 0);
    const unsigned long long hi = r0 > r1 ? r0 : r1;
    const unsigned long long lo = r0 > r1 ? r1 : r0;
    r0 = desc ? hi : lo;
    r1 = desc ? lo : hi;
}

// ---- 512-thread x 2-elem bitonic sort (desc) + top-300 decode ----
__device__ __forceinline__ void sort_emit(
    unsigned long long* s, int tid, int n,
    unsigned long long r0, unsigned long long r1,
    const float4* __restrict__ bx, const int* __restrict__ sizes,
    float* __restrict__ out)
{
    const int l  = tid & 31;
    const int w  = tid >> 5;
    const int i0 = w * 64 + l;
    const int i1 = i0 + 32;

    // k = 2..32 : pure shfl
    #pragma unroll
    for (int k = 2; k <= 32; k <<= 1)
        #pragma unroll
        for (int j = k >> 1; j >= 1; j >>= 1) {
            r0 = ushfl(r0, i0, j, k);
            r1 = ushfl(r1, i1, j, k);
        }
    // k = 64 : local j=32, then shfl
    ulocal32(r0, r1, i0, 64);
    #pragma unroll
    for (int j = 16; j >= 1; j >>= 1) {
        r0 = ushfl(r0, i0, j, 64);
        r1 = ushfl(r1, i1, j, 64);
    }
    // k = 128..1024 : smem for j>=64, local j=32, shfl j<=16
    #pragma unroll
    for (int k = 128; k <= CAP; k <<= 1) {
        s[i0] = r0; s[i1] = r1;
        __syncthreads();
        #pragma unroll
        for (int j = k >> 1; j >= 64; j >>= 1) {
            const unsigned long long o0 = s[i0 ^ j];
            const unsigned long long o1 = s[i1 ^ j];
            r0 = upick(r0, o0, i0, j, k);
            r1 = upick(r1, o1, i1, j, k);
            __syncthreads();                       // all reads done
            if (j > 64) { s[i0] = r0; s[i1] = r1; __syncthreads(); }
        }
        ulocal32(r0, r1, i0, k);
        #pragma unroll
        for (int j = 16; j >= 1; j >>= 1) {
            r0 = ushfl(r0, i0, j, k);
            r1 = ushfl(r1, i1, j, k);
        }
    }

    // epilogue: slots < 300 decode + write straight from registers
    const float fx = (float)sizes[1];
    const float fy = (float)sizes[0];
    #pragma unroll
    for (int e = 0; e < 2; e++) {
        const int slot = e ? i1 : i0;
        if (slot < TOPK) {
            const unsigned long long pk = e ? r1 : r0;
            const unsigned key  = (unsigned)(pk >> 32);
            const unsigned flat = 0xFFFFFFFFu - (unsigned)(pk & 0xFFFFFFFFu);
            const float lv    = key2f(key);
            const float score = 1.0f / (1.0f + __expf(-lv));
            const unsigned q   = flat / (unsigned)NCLS;
            const unsigned lbl = flat - q * (unsigned)NCLS;
            const float4 b = bx[(size_t)n * NQ + q];       // [cx, cy, w, h]
            float2* o = reinterpret_cast<float2*>(out + ((size_t)n * TOPK + slot) * 6);
            o[0] = make_float2((float)lbl, score);
            o[1] = make_float2((b.x - 0.5f * b.z) * fx, (b.y - 0.5f * b.w) * fy);
            o[2] = make_float2(b.z * fx, b.w * fy);
        }
    }
}

// ---- fused role-split kernel (expected shape only) ----
__global__ __launch_bounds__(SCTA, 3)
void scan_rank(const float4* __restrict__ lg,
               const float4* __restrict__ bx,
               const int*    __restrict__ sizes,
               float*        __restrict__ out)
{
    __shared__ union {
        unsigned long long s[CAP];      // 8KB: collect buf (first 384) + sort
        unsigned hist[NHIST];           // 16KB: fallback histogram
    } u;
    __shared__ int s_cnt;
    __shared__ int s_base;
    __shared__ unsigned s_tk;

    const int bid = blockIdx.x;
    const int t   = threadIdx.x;

    if (bid >= NB) {
        // ================= STREAMER =================
        const unsigned c   = (unsigned)(bid - NB);
        const unsigned n   = c >> 3;
        const unsigned seg = c & 7u;
        const unsigned f4base = n * (unsigned)NF4B + seg * (unsigned)SEGF4;

        if (t == 0) s_cnt = 0;
        __syncthreads();

        // 2500 = 4*512 + 452 : 4 full strides + partial 5th
        float4 v[5];
        #pragma unroll
        for (int k = 0; k < 4; k++) v[k] = lg[f4base + t + k * SCTA];
        const bool has5 = (t < (int)(SEGF4 - 4 * SCTA));   // t < 452
        if (has5) v[4] = lg[f4base + t + 4 * SCTA];

        #pragma unroll
        for (int k = 0; k < 5; k++) {
            if (k == 4 && !has5) continue;
            const float4 x = v[k];
            if (fmaxf(fmaxf(x.x, x.y), fmaxf(x.z, x.w)) > THR) {  // ~3.2%
                const unsigned loc0 = (seg * (unsigned)SEGF4 + (unsigned)t + (unsigned)k * SCTA) * 4u;
                if (x.x > THR) { int p = atomicAdd(&s_cnt, 1); if (p < BUFCAP) u.s[p] = pack(x.x, loc0 + 0u); }
                if (x.y > THR) { int p = atomicAdd(&s_cnt, 1); if (p < BUFCAP) u.s[p] = pack(x.y, loc0 + 1u); }
                if (x.z > THR) { int p = atomicAdd(&s_cnt, 1); if (p < BUFCAP) u.s[p] = pack(x.z, loc0 + 2u); }
                if (x.w > THR) { int p = atomicAdd(&s_cnt, 1); if (p < BUFCAP) u.s[p] = pack(x.w, loc0 + 3u); }
            }
        }
        __syncthreads();

        const int cnt = s_cnt;
        if (t == 0) {
            if (cnt > BUFCAP) {       // overflow -> poison count, force fallback
                atomicAdd(&g_cnt[n * GPAD], 1000000);
                s_base = -1;
            } else {
                s_base = atomicAdd(&g_cnt[n * GPAD], cnt);
            }
        }
        __syncthreads();

        const int base = s_base;
        if (base >= 0) {
            for (int i = t; i < cnt; i += SCTA) {
                const int p = base + i;
                if (p < CAP) g_cand[n][p] = u.s[i];   // >CAP -> fallback
            }
        }

        __syncthreads();                          // all flush stores issued
        if (t == 0) {
            __threadfence();                      // publish flush + count
            atomicAdd(&g_done[n * GPAD], 1);      // signal sorter
        }
        return;
    }

    // ================= SORTER (one per batch) =================
    const int n = bid;

    if (t == 0) {
        volatile int* done = &g_done[n * GPAD];
        while (*done < SEGS) __nanosleep(128);
        __threadfence();                          // acquire streamers' data
    }
    __syncthreads();

    const int l  = t & 31;
    const int w  = t >> 5;
    const int i0 = w * 64 + l;
    const int i1 = i0 + 32;

    const int bcnt = g_cnt[n * GPAD];
    const bool ok = (bcnt >= TOPK && bcnt <= CAP);
    unsigned long long r0 = 0, r1 = 0;

    if (ok) {
        r0 = (i0 < bcnt) ? g_cand[n][i0] : 0ULL;
        r1 = (i1 < bcnt) ? g_cand[n][i1] : 0ULL;
    }
    __syncthreads();                              // all bcnt/cand reads done
    if (t == 0) {                                 // reset for graph replay
        g_cnt[n * GPAD]  = 0;
        g_done[n * GPAD] = 0;
    }

    if (!ok) {
        // ---- exact fallback: histogram threshold + recollect ----
        const float4* fb = lg + (size_t)n * (NPB / 4);
        for (int i = t; i < NHIST; i += SCTA) u.hist[i] = 0u;
        if (t == 0) s_cnt = 0;
        __syncthreads();
        for (int i = t; i < NPB / 4; i += SCTA) {
            float4 x = fb[i];
            atomicAdd(&u.hist[fkey(x.x) >> 20], 1u);
            atomicAdd(&u.hist[fkey(x.y) >> 20], 1u);
            atomicAdd(&u.hist[fkey(x.z) >> 20], 1u);
            atomicAdd(&u.hist[fkey(x.w) >> 20], 1u);
        }
        __syncthreads();
        if (t == 0) {
            unsigned acc = 0; int b = NHIST - 1;
            for (; b > 0; --b) { acc += u.hist[b]; if (acc >= TOPK) break; }
            s_tk = (unsigned)b << 20;
        }
        __syncthreads();
        const unsigned tk = s_tk;
        for (int i = t; i < CAP; i += SCTA) u.s[i] = 0ULL;
        __syncthreads();
        for (int i = t; i < NPB / 4; i += SCTA) {
            float4 x = fb[i];
            const float e[4] = {x.x, x.y, x.z, x.w};
            #pragma unroll
            for (int j = 0; j < 4; j++) {
                unsigned kk = fkey(e[j]);
                if (kk >= tk) {
                    int p = atomicAdd(&s_cnt, 1);
                    if (p < CAP)
                        u.s[p] = ((unsigned long long)kk << 32) |
                                 (unsigned)(0xFFFFFFFFu - (unsigned)(4 * i + j));
                }
            }
        }
        __syncthreads();
        r0 = u.s[i0];
        r1 = u.s[i1];
        // safe: each thread reads only its own slots; the sort's first smem
        // write to those slots is by this same thread
    }

    sort_emit(u.s, t, n, r0, r1, bx, sizes, out);
}

// ================= generic-shape pipeline (unchanged) =================

__global__ __launch_bounds__(SCTA)
void scan_generic(const float4* __restrict__ lg, int total_f4)
{
    const unsigned S = gridDim.x * (unsigned)SCTA;
    for (unsigned i = blockIdx.x * SCTA + threadIdx.x; i < (unsigned)total_f4; i += S) {
        const float4 x = lg[i];
        if (fmaxf(fmaxf(x.x, x.y), fmaxf(x.z, x.w)) > THR) {
            const float e[4] = {x.x, x.y, x.z, x.w};
            #pragma unroll
            for (int j = 0; j < 4; j++) {
                if (e[j] > THR) {
                    const unsigned flat = i * 4u + (unsigned)j;
                    const unsigned n    = flat / (unsigned)NPB;
                    if (n < (unsigned)NB) {
                        const int p = atomicAdd(&g_cnt[n * GPAD], 1);
                        if (p < CAP)
                            g_cand[n][p] = pack(e[j], flat - n * (unsigned)NPB);
                    }
                }
            }
        }
    }
}

__global__ __launch_bounds__(SCTA)
void rank_kernel(const float4* __restrict__ lg,
                 const float4* __restrict__ bx,
                 const int*    __restrict__ sizes,
                 float*        __restrict__ out)
{
    __shared__ union {
        unsigned long long s[CAP];
        unsigned hist[NHIST];
    } u;
    __shared__ int s_c;
    __shared__ unsigned s_tk;

    const int n   = blockIdx.x;
    const int tid = threadIdx.x;
    const int l   = tid & 31;
    const int w   = tid >> 5;
    const int i0  = w * 64 + l;
    const int i1  = i0 + 32;

    const int cnt = (n < NB) ? g_cnt[n * GPAD] : -1;
    unsigned long long r0 = 0, r1 = 0;
    const bool ok = (cnt >= TOPK && cnt <= CAP);

    if (ok) {
        r0 = (i0 < cnt) ? g_cand[n][i0] : 0ULL;
        r1 = (i1 < cnt) ? g_cand[n][i1] : 0ULL;
    }
    __syncthreads();
    if (tid == 0 && n < NB) { g_cnt[n * GPAD] = 0; g_done[n * GPAD] = 0; }

    if (!ok) {
        const float4* base = lg + (size_t)n * (NPB / 4);
        for (int i = tid; i < NHIST; i += SCTA) u.hist[i] = 0u;
        if (tid == 0) s_c = 0;
        __syncthreads();
        for (int i = tid; i < NPB / 4; i += SCTA) {
            float4 x = base[i];
            atomicAdd(&u.hist[fkey(x.x) >> 20], 1u);
            atomicAdd(&u.hist[fkey(x.y) >> 20], 1u);
            atomicAdd(&u.hist[fkey(x.z) >> 20], 1u);
            atomicAdd(&u.hist[fkey(x.w) >> 20], 1u);
        }
        __syncthreads();
        if (tid == 0) {
            unsigned acc = 0; int b = NHIST - 1;
            for (; b > 0; --b) { acc += u.hist[b]; if (acc >= TOPK) break; }
            s_tk = (unsigned)b << 20;
        }
        __syncthreads();
        const unsigned tk = s_tk;
        for (int i = tid; i < CAP; i += SCTA) u.s[i] = 0ULL;
        __syncthreads();
        for (int i = tid; i < NPB / 4; i += SCTA) {
            float4 x = base[i];
            const float e[4] = {x.x, x.y, x.z, x.w};
            #pragma unroll
            for (int j = 0; j < 4; j++) {
                unsigned kk = fkey(e[j]);
                if (kk >= tk) {
                    int p = atomicAdd(&s_c, 1);
                    if (p < CAP)
                        u.s[p] = ((unsigned long long)kk << 32) |
                                 (unsigned)(0xFFFFFFFFu - (unsigned)(4 * i + j));
                }
            }
        }
        __syncthreads();
        r0 = u.s[i0];
        r1 = u.s[i1];
    }

    sort_emit(u.s, tid, n, r0, r1, bx, sizes, out);
}

extern "C" void kernel_launch(void* const* d_in, const int* in_sizes, int n_in,
                              void* d_out, int out_size)
{
    const float* logits = (const float*)d_in[0];
    const float* boxes  = (const float*)d_in[1];
    const int*   sizes  = (const int*)d_in[2];
    const int total     = in_sizes[0];
    const int N         = total / NPB;

    if (total == NB * NPB) {
        scan_rank<<<NB + NB * SEGS, SCTA>>>((const float4*)logits,
                                            (const float4*)boxes, sizes,
                                            (float*)d_out);
    } else {
        const int total_f4 = total / 4;
        int grid = (total_f4 + SCTA - 1) / SCTA;
        if (grid > 2048) grid = 2048;
        if (grid < 1) grid = 1;
        scan_generic<<<grid, SCTA>>>((const float4*)logits, total_f4);
        rank_kernel<<<N, SCTA>>>((const float4*)logits, (const float4*)boxes,
                                 sizes, (float*)d_out);
    }
}

// round 12
// speedup vs baseline: 1.7347x; 1.7347x over previous
#include <cuda_runtime.h>
#include <cuda_bf16.h>

// DETR post-processor, 2-launch pipeline with PDL overlap:
//   scan_batched : 1 CTA per batch-segment (8 x 2500 float4/batch), FMNMX
//                  screen at t=2.576 (lambda=400) -> smem buffer via smem
//                  atomics; ONE global atomic reserves a g_cand block,
//                  coalesced flush; fence + griddepcontrol.launch_dependents.
//                  Streaming measured at the LTS ceiling (~6.3 TB/s).
//   rank_kernel  : launched with programmatic-stream-serialization. Prologue
//                  (boxes[1000] -> smem prefetch) runs DURING scan's tail;
//                  griddepcontrol.wait gates only the candidate reads.
//                  Bitonic sort of 512 packed u64 (256 thr x 2: shfl j<=16,
//                  local j=32, smem j>=64 -> 6 smem phases), top-300 decoded
//                  straight from registers against smem boxes. Exact
//                  histogram fallback if count outside [300,512]
//                  (lambda=400, sigma=20 -> both bounds >=5 sigma).

#define NCLS    80
#define NQ      1000
#define NPB     80000
#define NF4B    20000          // float4 per batch
#define NB      256
#define TOPK    300
#define CAP     512
#define THR     2.576f
#define SEGS    8              // streamer CTAs per batch
#define SEGF4   2500           // float4 per streamer CTA
#define SCTA    512
#define RTHREADS 256
#define BUFCAP  384            // smem candidate buffer (seg lambda=50)
#define GPAD    32             // counter stride (128B) -> spread LTS slices
#define NHIST   4096

__device__ unsigned long long g_cand[NB][CAP];
__device__ int g_cnt[NB * GPAD];

__device__ __forceinline__ unsigned fkey(float f) {
    unsigned u = __float_as_uint(f);
    return (u & 0x80000000u) ? ~u : (u | 0x80000000u);  // monotonic float->uint
}
__device__ __forceinline__ float key2f(unsigned k) {
    return (k & 0x80000000u) ? __uint_as_float(k & 0x7fffffffu)
                             : __uint_as_float(~k);
}
__device__ __forceinline__ unsigned long long pack(float val, unsigned loc) {
    return ((unsigned long long)fkey(val) << 32) | (unsigned)(0xFFFFFFFFu - loc);
}

// ---- batch-aligned scan: CTA c covers batch c/8, segment c%8 ----
__global__ __launch_bounds__(SCTA, 3)
void scan_batched(const float4* __restrict__ lg)
{
    __shared__ unsigned long long s_buf[BUFCAP];
    __shared__ int s_cnt;
    __shared__ int s_base;

    const unsigned c   = blockIdx.x;
    const unsigned n   = c >> 3;
    const unsigned seg = c & 7u;
    const unsigned t   = threadIdx.x;
    const unsigned f4base = n * (unsigned)NF4B + seg * (unsigned)SEGF4;

    if (t == 0) s_cnt = 0;
    __syncthreads();

    // 2500 = 4*512 + 452 : 4 full strides + partial 5th
    float4 v[5];
    #pragma unroll
    for (int k = 0; k < 4; k++) v[k] = lg[f4base + t + k * SCTA];
    const bool has5 = (t < (unsigned)(SEGF4 - 4 * SCTA));   // t < 452
    if (has5) v[4] = lg[f4base + t + 4 * SCTA];

    #pragma unroll
    for (int k = 0; k < 5; k++) {
        if (k == 4 && !has5) continue;
        const float4 x = v[k];
        if (fmaxf(fmaxf(x.x, x.y), fmaxf(x.z, x.w)) > THR) {  // ~2% taken
            const unsigned loc0 = (seg * (unsigned)SEGF4 + t + (unsigned)k * SCTA) * 4u;
            if (x.x > THR) { int p = atomicAdd(&s_cnt, 1); if (p < BUFCAP) s_buf[p] = pack(x.x, loc0 + 0u); }
            if (x.y > THR) { int p = atomicAdd(&s_cnt, 1); if (p < BUFCAP) s_buf[p] = pack(x.y, loc0 + 1u); }
            if (x.z > THR) { int p = atomicAdd(&s_cnt, 1); if (p < BUFCAP) s_buf[p] = pack(x.z, loc0 + 2u); }
            if (x.w > THR) { int p = atomicAdd(&s_cnt, 1); if (p < BUFCAP) s_buf[p] = pack(x.w, loc0 + 3u); }
        }
    }
    __syncthreads();

    const int cnt = s_cnt;
    if (t == 0) {
        if (cnt > BUFCAP) {           // overflow -> poison count, force fallback
            atomicAdd(&g_cnt[n * GPAD], 1000000);
            s_base = -1;
        } else {
            s_base = atomicAdd(&g_cnt[n * GPAD], cnt);
        }
    }
    __syncthreads();

    const int base = s_base;
    if (base >= 0) {
        for (int i = (int)t; i < cnt; i += SCTA) {
            const int p = base + i;
            if (p < CAP) g_cand[n][p] = s_buf[i];   // >CAP handled by fallback
        }
    }

    // publish results, then allow the dependent rank launch
    __syncthreads();
    __threadfence();
    asm volatile("griddepcontrol.launch_dependents;");
}

// ---- generic fallback scan for unexpected sizes ----
__global__ __launch_bounds__(SCTA)
void scan_generic(const float4* __restrict__ lg, int total_f4)
{
    const unsigned S = gridDim.x * (unsigned)SCTA;
    for (unsigned i = blockIdx.x * SCTA + threadIdx.x; i < (unsigned)total_f4; i += S) {
        const float4 x = lg[i];
        if (fmaxf(fmaxf(x.x, x.y), fmaxf(x.z, x.w)) > THR) {
            const float e[4] = {x.x, x.y, x.z, x.w};
            #pragma unroll
            for (int j = 0; j < 4; j++) {
                if (e[j] > THR) {
                    const unsigned flat = i * 4u + (unsigned)j;
                    const unsigned n    = flat / (unsigned)NPB;
                    if (n < (unsigned)NB) {
                        const int p = atomicAdd(&g_cnt[n * GPAD], 1);
                        if (p < CAP)
                            g_cand[n][p] = pack(e[j], flat - n * (unsigned)NPB);
                    }
                }
            }
        }
    }
    __threadfence();
    asm volatile("griddepcontrol.launch_dependents;");
}

// ---- bitonic helpers (element index i, phase j, block k) ----
__device__ __forceinline__ unsigned long long upick(
    unsigned long long v, unsigned long long o, int i, int j, int k)
{
    const bool keep_max = (((i & j) == 0) == ((i & k) == 0));
    const unsigned long long mx = v > o ? v : o;
    const unsigned long long mn = v > o ? o : v;
    return keep_max ? mx : mn;
}
__device__ __forceinline__ unsigned long long ushfl(
    unsigned long long v, int i, int j, int k)
{
    const unsigned long long o = __shfl_xor_sync(0xFFFFFFFFu, v, j);
    return upick(v, o, i, j, k);
}
__device__ __forceinline__ void ulocal32(
    unsigned long long& r0, unsigned long long& r1, int i0, int k)
{
    const bool desc = ((i0 & k) == 0);
    const unsigned long long hi = r0 > r1 ? r0 : r1;
    const unsigned long long lo = r0 > r1 ? r1 : r0;
    r0 = desc ? hi : lo;
    r1 = desc ? lo : hi;
}

__global__ __launch_bounds__(RTHREADS)
void rank_kernel(const float4* __restrict__ lg,
                 const float4* __restrict__ bx,
                 const int*    __restrict__ sizes,
                 float*        __restrict__ out)
{
    __shared__ float4 sbx[NQ];          // 16KB: prefetched boxes
    __shared__ union {
        unsigned long long s[CAP];      // 4KB: sort exchange
        unsigned hist[NHIST];           // 16KB: fallback histogram
    } u;
    __shared__ int s_c;
    __shared__ unsigned s_tk;

    const int n   = blockIdx.x;
    const int tid = threadIdx.x;
    const int l   = tid & 31;
    const int w   = tid >> 5;           // 8 warps
    const int i0  = w * 64 + l;         // slots i0, i0+32 cover 0..511
    const int i1  = i0 + 32;

    // ---- prologue (scan-independent): prefetch boxes during scan tail ----
    const float fx = (float)sizes[1];
    const float fy = (float)sizes[0];
    for (int i = tid; i < NQ; i += RTHREADS)
        sbx[i] = bx[(size_t)n * NQ + i];

    // gate: everything below reads scan output
    asm volatile("griddepcontrol.wait;" ::: "memory");

    // issue count + candidate loads concurrently (stale tails masked below)
    const int cnt = g_cnt[n * GPAD];
    unsigned long long c0 = g_cand[n][i0];
    unsigned long long c1 = g_cand[n][i1];
    const bool ok = (cnt >= TOPK && cnt <= CAP);
    unsigned long long r0 = (ok && i0 < cnt) ? c0 : 0ULL;
    unsigned long long r1 = (ok && i1 < cnt) ? c1 : 0ULL;

    __syncthreads();                    // all cnt/cand reads done
    if (tid == 0) g_cnt[n * GPAD] = 0;  // reset for next graph replay

    if (!ok) {
        // ---- exact fallback: histogram threshold + recollect ----
        const float4* base = lg + (size_t)n * (NPB / 4);
        for (int i = tid; i < NHIST; i += RTHREADS) u.hist[i] = 0u;
        if (tid == 0) s_c = 0;
        __syncthreads();
        for (int i = tid; i < NPB / 4; i += RTHREADS) {
            float4 x = base[i];
            atomicAdd(&u.hist[fkey(x.x) >> 20], 1u);
            atomicAdd(&u.hist[fkey(x.y) >> 20], 1u);
            atomicAdd(&u.hist[fkey(x.z) >> 20], 1u);
            atomicAdd(&u.hist[fkey(x.w) >> 20], 1u);
        }
        __syncthreads();
        if (tid == 0) {
            unsigned acc = 0; int b = NHIST - 1;
            for (; b > 0; --b) { acc += u.hist[b]; if (acc >= TOPK) break; }
            s_tk = (unsigned)b << 20;
        }
        __syncthreads();
        const unsigned tk = s_tk;
        for (int i = tid; i < CAP; i += RTHREADS) u.s[i] = 0ULL;
        __syncthreads();
        for (int i = tid; i < NPB / 4; i += RTHREADS) {
            float4 x = base[i];
            const float e[4] = {x.x, x.y, x.z, x.w};
            #pragma unroll
            for (int j = 0; j < 4; j++) {
                unsigned kk = fkey(e[j]);
                if (kk >= tk) {
                    int p = atomicAdd(&s_c, 1);
                    if (p < CAP)
                        u.s[p] = ((unsigned long long)kk << 32) |
                                 (unsigned)(0xFFFFFFFFu - (unsigned)(4 * i + j));
                }
            }
        }
        __syncthreads();
        r0 = u.s[i0];
        r1 = u.s[i1];
        // safe: each thread reads only its own slots; the sort's first smem
        // write to those slots is by this same thread
    }

    // ---- bitonic sort, descending, 512 elems, 2 per thread ----
    // k = 2..32 : pure shfl
    #pragma unroll
    for (int k = 2; k <= 32; k <<= 1)
        #pragma unroll
        for (int j = k >> 1; j >= 1; j >>= 1) {
            r0 = ushfl(r0, i0, j, k);
            r1 = ushfl(r1, i1, j, k);
        }
    // k = 64 : local j=32, then shfl
    ulocal32(r0, r1, i0, 64);
    #pragma unroll
    for (int j = 16; j >= 1; j >>= 1) {
        r0 = ushfl(r0, i0, j, 64);
        r1 = ushfl(r1, i1, j, 64);
    }
    // k = 128..512 : smem for j>=64, local j=32, shfl j<=16
    #pragma unroll
    for (int k = 128; k <= CAP; k <<= 1) {
        u.s[i0] = r0; u.s[i1] = r1;
        __syncthreads();
        #pragma unroll
        for (int j = k >> 1; j >= 64; j >>= 1) {
            const unsigned long long o0 = u.s[i0 ^ j];
            const unsigned long long o1 = u.s[i1 ^ j];
            r0 = upick(r0, o0, i0, j, k);
            r1 = upick(r1, o1, i1, j, k);
            __syncthreads();                       // all reads done
            if (j > 64) { u.s[i0] = r0; u.s[i1] = r1; __syncthreads(); }
        }
        ulocal32(r0, r1, i0, k);
        #pragma unroll
        for (int j = 16; j >= 1; j >>= 1) {
            r0 = ushfl(r0, i0, j, k);
            r1 = ushfl(r1, i1, j, k);
        }
    }

    // ---- epilogue: slots < 300 decode + write straight from registers ----
    #pragma unroll
    for (int e = 0; e < 2; e++) {
        const int slot = e ? i1 : i0;
        if (slot < TOPK) {
            const unsigned long long pk = e ? r1 : r0;
            const unsigned key  = (unsigned)(pk >> 32);
            const unsigned flat = 0xFFFFFFFFu - (unsigned)(pk & 0xFFFFFFFFu);
            const float lv    = key2f(key);
            const float score = 1.0f / (1.0f + __expf(-lv));
            const unsigned q   = flat / (unsigned)NCLS;
            const unsigned lbl = flat - q * (unsigned)NCLS;
            const float4 b = sbx[q];                       // [cx, cy, w, h]
            float2* o = reinterpret_cast<float2*>(out + ((size_t)n * TOPK + slot) * 6);
            o[0] = make_float2((float)lbl, score);
            o[1] = make_float2((b.x - 0.5f * b.z) * fx, (b.y - 0.5f * b.w) * fy);
            o[2] = make_float2(b.z * fx, b.w * fy);
        }
    }
}

extern "C" void kernel_launch(void* const* d_in, const int* in_sizes, int n_in,
                              void* d_out, int out_size)
{
    const float* logits = (const float*)d_in[0];
    const float* boxes  = (const float*)d_in[1];
    const int*   sizes  = (const int*)d_in[2];
    const int total     = in_sizes[0];
    const int N         = total / NPB;

    if (total == NB * NPB) {
        scan_batched<<<NB * SEGS, SCTA>>>((const float4*)logits);
    } else {
        const int total_f4 = total / 4;
        int grid = (total_f4 + SCTA - 1) / SCTA;
        if (grid > 2048) grid = 2048;
        if (grid < 1) grid = 1;
        scan_generic<<<grid, SCTA>>>((const float4*)logits, total_f4);
    }

    // rank: PDL-serialized so its prologue overlaps the scan's tail
    cudaLaunchConfig_t cfg = {};
    cfg.gridDim  = dim3((unsigned)N, 1, 1);
    cfg.blockDim = dim3(RTHREADS, 1, 1);
    cfg.dynamicSmemBytes = 0;
    cfg.stream = 0;
    cudaLaunchAttribute attr[1];
    attr[0].id = cudaLaunchAttributeProgrammaticStreamSerialization;
    attr[0].val.programmaticStreamSerializationAllowed = 1;
    cfg.attrs = attr;
    cfg.numAttrs = 1;
    cudaLaunchKernelEx(&cfg, rank_kernel,
                       (const float4*)logits, (const float4*)boxes,
                       sizes, (float*)d_out);
}